// round 9
// baseline (speedup 1.0000x reference)
#include <cuda_runtime.h>

// ---------------------------------------------------------------------------
// GCN_13898514169996: 2-layer GCN, N=100000, E=3.2M, 512->16->7.
// gcn(h)[v] = dinv[v] * ( sum_{u->v} h[u]*dinv[u] + h[v]*dinv[v] ) + b
// dinv = rsqrt(cnt[v]+1). edge_index int32. Round 9: fused pipeline,
// 7 kernels: zero, count, scan(lookback), place, gemm1, gl1, gl2.
// ---------------------------------------------------------------------------

#define MAXN 100000
#define MAXE 3200000

__device__ float g_hs  [MAXN * 16];  // (X@W1) * dinv[row]
__device__ float g_hs2 [MAXN * 8];   // (h1@W2) * dinv[row], padded to 8
__device__ int   g_cnt [MAXN];       // in-degree (excl. self loop)
__device__ int   g_off [MAXN];       // CSR offsets
__device__ int   g_cur [MAXN];       // placement cursors
__device__ int   g_eadj[MAXE];       // CSR adjacency: src ids grouped by dst
__device__ unsigned long long g_scanpack[512];  // lookback state

// ---- zero counts + scan flags ----------------------------------------------------
__global__ void k_zero(int n) {
    int v = blockIdx.x * blockDim.x + threadIdx.x;
    if (v < n) g_cnt[v] = 0;
    if (v < 512) g_scanpack[v] = 0ull;
}

__global__ void k_count(const int* __restrict__ dst, int E) {
    int i = blockIdx.x * blockDim.x + threadIdx.x;
    if (i >= E) return;
    atomicAdd(&g_cnt[dst[i]], 1);
}

// ---- single-pass exclusive scan (decoupled lookback) ------------------------------
// pack = (value << 2) | state; state: 0 invalid, 1 aggregate, 2 inclusive.
__global__ void __launch_bounds__(256) k_scan(int n) {
    __shared__ int warp_tot[8];
    __shared__ int s_excl;
    int t = threadIdx.x, b = blockIdx.x;
    int v = b * 256 + t;
    int val = (v < n) ? g_cnt[v] : 0;

    int lane = t & 31, w = t >> 5;
    int x = val;
    #pragma unroll
    for (int d = 1; d < 32; d <<= 1) {
        int y = __shfl_up_sync(0xffffffffu, x, d);
        if (lane >= d) x += y;
    }
    if (lane == 31) warp_tot[w] = x;
    __syncthreads();
    if (w == 0) {
        int wt = (lane < 8) ? warp_tot[lane] : 0;
        #pragma unroll
        for (int d = 1; d < 8; d <<= 1) {
            int y = __shfl_up_sync(0xffffffffu, wt, d);
            if (lane >= d) wt += y;
        }
        if (lane < 8) warp_tot[lane] = wt;   // inclusive totals per warp
    }
    __syncthreads();

    int local_excl  = x - val + ((w > 0) ? warp_tot[w - 1] : 0);
    int block_total = warp_tot[7];

    if (t == 0) {
        atomicExch(&g_scanpack[b], ((unsigned long long)block_total << 2) | 1ull);
        long long run = 0;
        int j = b - 1;
        while (j >= 0) {
            unsigned long long pk;
            do { pk = atomicAdd(&g_scanpack[j], 0ull); } while ((pk & 3ull) == 0ull);
            run += (long long)(pk >> 2);
            if ((pk & 3ull) == 2ull) break;
            j--;
        }
        s_excl = (int)run;
        atomicExch(&g_scanpack[b],
                   ((unsigned long long)(run + block_total) << 2) | 2ull);
    }
    __syncthreads();

    if (v < n) {
        int o = s_excl + local_excl;
        g_off[v] = o;
        g_cur[v] = o;
    }
}

// ---- CSR placement ------------------------------------------------------------------
__global__ void k_place(const int* __restrict__ src,
                        const int* __restrict__ dst, int E) {
    int e = blockIdx.x * blockDim.x + threadIdx.x;
    if (e >= E) return;
    int slot = atomicAdd(&g_cur[dst[e]], 1);
    g_eadj[slot] = src[e];
}

// ---- GEMM1: hs = (X @ W1) * dinv[row] -------------------------------------------------
__global__ void __launch_bounds__(128, 7) k_gemm1(const float* __restrict__ x,
                                                  const float* __restrict__ W1,
                                                  int n) {
    __shared__ float Xs[128 * 36];   // [row][k_local] stride 36 (pad 4)
    __shared__ float Wsc[32 * 16];   // [k_local][col]

    int t    = threadIdx.x;
    int c    = t & 3;
    int rg   = t >> 2;
    int row0 = blockIdx.x * 128;

    float acc[4][4];
    #pragma unroll
    for (int i = 0; i < 4; i++)
        #pragma unroll
        for (int j = 0; j < 4; j++) acc[i][j] = 0.f;

    int sq  = t & 7;
    int sr  = t >> 3;
    int wkl = t >> 2;
    int wjj = (t & 3) * 4;

    #pragma unroll 1
    for (int ch = 0; ch < 16; ch++) {
        int k0 = ch * 32;
        __syncthreads();
        *(float4*)(Wsc + wkl * 16 + wjj) =
            *(const float4*)(W1 + (size_t)(k0 + wkl) * 16 + wjj);
        #pragma unroll
        for (int p = 0; p < 8; p++) {
            int rl = p * 16 + sr;
            int gr = row0 + rl; if (gr > n - 1) gr = n - 1;
            float4 v = __ldg((const float4*)(x + (size_t)gr * 512 + k0) + sq);
            *(float4*)(Xs + rl * 36 + sq * 4) = v;
        }
        __syncthreads();

        #pragma unroll
        for (int k4 = 0; k4 < 8; k4++) {
            float4 w0 = *(float4*)(Wsc + (k4 * 4 + 0) * 16 + c * 4);
            float4 w1 = *(float4*)(Wsc + (k4 * 4 + 1) * 16 + c * 4);
            float4 w2 = *(float4*)(Wsc + (k4 * 4 + 2) * 16 + c * 4);
            float4 w3 = *(float4*)(Wsc + (k4 * 4 + 3) * 16 + c * 4);
            #pragma unroll
            for (int i = 0; i < 4; i++) {
                float4 xv = *(float4*)(Xs + (rg + 32 * i) * 36 + k4 * 4);
                acc[i][0] += xv.x * w0.x + xv.y * w1.x + xv.z * w2.x + xv.w * w3.x;
                acc[i][1] += xv.x * w0.y + xv.y * w1.y + xv.z * w2.y + xv.w * w3.y;
                acc[i][2] += xv.x * w0.z + xv.y * w1.z + xv.z * w2.z + xv.w * w3.z;
                acc[i][3] += xv.x * w0.w + xv.y * w1.w + xv.z * w2.w + xv.w * w3.w;
            }
        }
    }

    #pragma unroll
    for (int i = 0; i < 4; i++) {
        int row = row0 + rg + 32 * i;
        if (row >= n) continue;
        float dv = rsqrtf((float)g_cnt[row] + 1.f);
        float4 o = make_float4(acc[i][0] * dv, acc[i][1] * dv,
                               acc[i][2] * dv, acc[i][3] * dv);
        *(float4*)(g_hs + (size_t)row * 16 + c * 4) = o;
    }
}

// ---- fused gather1 + layer-1 epilogue + layer-2 GEMM ---------------------------------
// 4 threads/node (quarter each). Gather coalesced, then h1 = relu(dv*(sum+self)+b1),
// partial 16->7 GEMM per quarter, butterfly-reduced across the 4 lanes,
// hs2 = o * dv written by lanes q=0 (cols 0-3) and q=1 (cols 4-6, pad 0).
__global__ void __launch_bounds__(256) k_gl1(const float* __restrict__ b1,
                                             const float* __restrict__ W2,
                                             int n) {
    __shared__ float W2s[112];
    __shared__ float b1s[16];
    int t = threadIdx.x;
    if (t < 112) W2s[t] = W2[t];
    if (t < 16)  b1s[t] = b1[t];
    __syncthreads();

    int gi = blockIdx.x * 256 + t;
    int v  = gi >> 2;
    if (v >= n) return;
    int q   = gi & 3;
    int off = g_off[v];
    int cnt = g_cnt[v];

    // gather quarter
    float4 acc = make_float4(0.f, 0.f, 0.f, 0.f);
    int i = 0;
    for (; i + 2 <= cnt; i += 2) {
        int s0 = g_eadj[off + i];
        int s1 = g_eadj[off + i + 1];
        float4 a = __ldg((const float4*)(g_hs + (size_t)s0 * 16) + q);
        float4 b = __ldg((const float4*)(g_hs + (size_t)s1 * 16) + q);
        acc.x += a.x + b.x; acc.y += a.y + b.y;
        acc.z += a.z + b.z; acc.w += a.w + b.w;
    }
    if (i < cnt) {
        int s0 = g_eadj[off + i];
        float4 a = __ldg((const float4*)(g_hs + (size_t)s0 * 16) + q);
        acc.x += a.x; acc.y += a.y; acc.z += a.z; acc.w += a.w;
    }

    // epilogue: + self, *dv, +b1, relu
    float dv = rsqrtf((float)cnt + 1.f);
    float4 self = *(const float4*)(g_hs + (size_t)v * 16 + q * 4);
    float h0 = fmaxf(fmaf(dv, acc.x + self.x, b1s[q * 4 + 0]), 0.f);
    float h1 = fmaxf(fmaf(dv, acc.y + self.y, b1s[q * 4 + 1]), 0.f);
    float h2 = fmaxf(fmaf(dv, acc.z + self.z, b1s[q * 4 + 2]), 0.f);
    float h3 = fmaxf(fmaf(dv, acc.w + self.w, b1s[q * 4 + 3]), 0.f);

    // partial 16->7 GEMM over this quarter's 4 k values
    float o[7];
    #pragma unroll
    for (int j = 0; j < 7; j++) {
        const float* wq = W2s + (q * 4) * 7 + j;
        o[j] = h0 * wq[0] + h1 * wq[7] + h2 * wq[14] + h3 * wq[21];
    }
    // butterfly reduce across the 4 lanes of this node
    #pragma unroll
    for (int j = 0; j < 7; j++) {
        o[j] += __shfl_xor_sync(0xffffffffu, o[j], 1);
        o[j] += __shfl_xor_sync(0xffffffffu, o[j], 2);
    }

    if (q == 0)
        *(float4*)(g_hs2 + (size_t)v * 8) =
            make_float4(o[0] * dv, o[1] * dv, o[2] * dv, o[3] * dv);
    else if (q == 1)
        *(float4*)(g_hs2 + (size_t)v * 8 + 4) =
            make_float4(o[4] * dv, o[5] * dv, o[6] * dv, 0.f);
}

// ---- fused gather2 + final (bias + log_softmax) ---------------------------------------
// 2 threads/node. Each gathers its half of hs2, computes its 4 logits, exchanges
// halves via shfl_xor, then computes log_softmax and writes its own 4/3 outputs.
__global__ void __launch_bounds__(256) k_gl2(const float* __restrict__ b2,
                                             float* __restrict__ out, int n) {
    int gi = blockIdx.x * 256 + threadIdx.x;
    int v  = gi >> 1;
    if (v >= n) return;
    int q   = gi & 1;
    int off = g_off[v];
    int cnt = g_cnt[v];

    float4 acc = make_float4(0.f, 0.f, 0.f, 0.f);
    int i = 0;
    for (; i + 2 <= cnt; i += 2) {
        int s0 = g_eadj[off + i];
        int s1 = g_eadj[off + i + 1];
        float4 a = __ldg((const float4*)(g_hs2 + (size_t)s0 * 8) + q);
        float4 b = __ldg((const float4*)(g_hs2 + (size_t)s1 * 8) + q);
        acc.x += a.x + b.x; acc.y += a.y + b.y;
        acc.z += a.z + b.z; acc.w += a.w + b.w;
    }
    if (i < cnt) {
        int s0 = g_eadj[off + i];
        float4 a = __ldg((const float4*)(g_hs2 + (size_t)s0 * 8) + q);
        acc.x += a.x; acc.y += a.y; acc.z += a.z; acc.w += a.w;
    }

    float dv = rsqrtf((float)cnt + 1.f);
    float4 self = *(const float4*)(g_hs2 + (size_t)v * 8 + q * 4);
    float m0 = fmaf(dv, acc.x + self.x, __ldg(b2 + q * 4 + 0));
    float m1 = fmaf(dv, acc.y + self.y, __ldg(b2 + q * 4 + 1));
    float m2 = fmaf(dv, acc.z + self.z, __ldg(b2 + q * 4 + 2));
    float m3 = (q == 0) ? fmaf(dv, acc.w + self.w, __ldg(b2 + 3)) : -1e30f;

    // exchange halves (paired lanes 2v, 2v+1)
    float p0 = __shfl_xor_sync(0xffffffffu, m0, 1);
    float p1 = __shfl_xor_sync(0xffffffffu, m1, 1);
    float p2 = __shfl_xor_sync(0xffffffffu, m2, 1);
    float p3 = __shfl_xor_sync(0xffffffffu, m3, 1);

    float mx = fmaxf(fmaxf(fmaxf(m0, m1), fmaxf(m2, m3)),
                     fmaxf(fmaxf(p0, p1), fmaxf(p2, p3)));
    float s = expf(m0 - mx) + expf(m1 - mx) + expf(m2 - mx) +
              expf(p0 - mx) + expf(p1 - mx) + expf(p2 - mx);
    s += (q == 0) ? expf(m3 - mx) : expf(p3 - mx);
    float l = logf(s) + mx;

    float* ov = out + (size_t)v * 7 + q * 4;
    ov[0] = m0 - l;
    ov[1] = m1 - l;
    ov[2] = m2 - l;
    if (q == 0) ov[3] = m3 - l;
}

// ---------------------------------------------------------------------------
extern "C" void kernel_launch(void* const* d_in, const int* in_sizes, int n_in,
                              void* d_out, int out_size) {
    const float* x  = (const float*)d_in[0];
    const int*   ei = (const int*)d_in[1];      // int32 (JAX x64 disabled)
    const float* W1 = (const float*)d_in[2];
    const float* b1 = (const float*)d_in[3];
    const float* W2 = (const float*)d_in[4];
    const float* b2 = (const float*)d_in[5];

    int n = in_sizes[0] / 512;     // 100000
    int E = in_sizes[1] / 2;       // 3200000
    const int* src = ei;
    const int* dst = ei + E;

    int nb = (n + 255) / 256;
    int eb = (E + 255) / 256;

    k_zero <<<nb, 256>>>(n);
    k_count<<<eb, 256>>>(dst, E);
    k_scan <<<nb, 256>>>(n);
    k_place<<<eb, 256>>>(src, dst, E);
    k_gemm1<<<(n + 127) / 128, 128>>>(x, W1, n);
    k_gl1  <<<(4 * n + 255) / 256, 256>>>(b1, W2, n);
    k_gl2  <<<(2 * n + 255) / 256, 256>>>(b2, (float*)d_out, n);
}

// round 10
// speedup vs baseline: 1.0573x; 1.0573x over previous
#include <cuda_runtime.h>

// ---------------------------------------------------------------------------
// GCN_13898514169996: 2-layer GCN, N=100000, E=3.2M, 512->16->7.
// gcn(h)[v] = dinv[v] * ( sum_{u->v} h[u]*dinv[u] + h[v]*dinv[v] ) + b
// dinv = rsqrt(cnt[v]+1). edge_index int32.
// Round 10: 4-edge ILP in count/place + stream overlap (CSR build || GEMM1).
// ---------------------------------------------------------------------------

#define MAXN 100000
#define MAXE 3200000

__device__ float g_hs  [MAXN * 16];  // (X@W1) * dinv[row]
__device__ float g_hs2 [MAXN * 8];   // (h1@W2) * dinv[row], padded to 8
__device__ int   g_cnt [MAXN];       // in-degree (excl. self loop)
__device__ int   g_off [MAXN];       // CSR offsets
__device__ int   g_cur [MAXN];       // placement cursors
__device__ int   g_eadj[MAXE];       // CSR adjacency: src ids grouped by dst
__device__ unsigned long long g_scanpack[512];  // lookback state

// ---- zero counts + scan flags ----------------------------------------------------
__global__ void k_zero(int n) {
    int v = blockIdx.x * blockDim.x + threadIdx.x;
    if (v < n) g_cnt[v] = 0;
    if (v < 512) g_scanpack[v] = 0ull;
}

// ---- in-degree count, 4 edges/thread ----------------------------------------------
__global__ void k_count(const int* __restrict__ dst, int E) {
    int i = blockIdx.x * blockDim.x + threadIdx.x;
    int e0 = i * 4;
    if (e0 + 3 < E) {
        int4 d = __ldg((const int4*)dst + i);
        atomicAdd(&g_cnt[d.x], 1);
        atomicAdd(&g_cnt[d.y], 1);
        atomicAdd(&g_cnt[d.z], 1);
        atomicAdd(&g_cnt[d.w], 1);
    } else {
        for (int e = e0; e < E; e++) atomicAdd(&g_cnt[dst[e]], 1);
    }
}

// ---- single-pass exclusive scan (decoupled lookback) -------------------------------
__global__ void __launch_bounds__(256) k_scan(int n) {
    __shared__ int warp_tot[8];
    __shared__ int s_excl;
    int t = threadIdx.x, b = blockIdx.x;
    int v = b * 256 + t;
    int val = (v < n) ? g_cnt[v] : 0;

    int lane = t & 31, w = t >> 5;
    int x = val;
    #pragma unroll
    for (int d = 1; d < 32; d <<= 1) {
        int y = __shfl_up_sync(0xffffffffu, x, d);
        if (lane >= d) x += y;
    }
    if (lane == 31) warp_tot[w] = x;
    __syncthreads();
    if (w == 0) {
        int wt = (lane < 8) ? warp_tot[lane] : 0;
        #pragma unroll
        for (int d = 1; d < 8; d <<= 1) {
            int y = __shfl_up_sync(0xffffffffu, wt, d);
            if (lane >= d) wt += y;
        }
        if (lane < 8) warp_tot[lane] = wt;
    }
    __syncthreads();

    int local_excl  = x - val + ((w > 0) ? warp_tot[w - 1] : 0);
    int block_total = warp_tot[7];

    if (t == 0) {
        atomicExch(&g_scanpack[b], ((unsigned long long)block_total << 2) | 1ull);
        long long run = 0;
        int j = b - 1;
        while (j >= 0) {
            unsigned long long pk;
            do { pk = atomicAdd(&g_scanpack[j], 0ull); } while ((pk & 3ull) == 0ull);
            run += (long long)(pk >> 2);
            if ((pk & 3ull) == 2ull) break;
            j--;
        }
        s_excl = (int)run;
        atomicExch(&g_scanpack[b],
                   ((unsigned long long)(run + block_total) << 2) | 2ull);
    }
    __syncthreads();

    if (v < n) {
        int o = s_excl + local_excl;
        g_off[v] = o;
        g_cur[v] = o;
    }
}

// ---- CSR placement, 4 edges/thread (4 independent ATOMG chains) --------------------
__global__ void k_place(const int* __restrict__ src,
                        const int* __restrict__ dst, int E) {
    int i = blockIdx.x * blockDim.x + threadIdx.x;
    int e0 = i * 4;
    if (e0 + 3 < E) {
        int4 d = __ldg((const int4*)dst + i);
        int4 s = __ldg((const int4*)src + i);
        int sl0 = atomicAdd(&g_cur[d.x], 1);
        int sl1 = atomicAdd(&g_cur[d.y], 1);
        int sl2 = atomicAdd(&g_cur[d.z], 1);
        int sl3 = atomicAdd(&g_cur[d.w], 1);
        g_eadj[sl0] = s.x;
        g_eadj[sl1] = s.y;
        g_eadj[sl2] = s.z;
        g_eadj[sl3] = s.w;
    } else {
        for (int e = e0; e < E; e++) {
            int slot = atomicAdd(&g_cur[dst[e]], 1);
            g_eadj[slot] = src[e];
        }
    }
}

// ---- GEMM1: hs = (X @ W1) * dinv[row] -----------------------------------------------
__global__ void __launch_bounds__(128, 7) k_gemm1(const float* __restrict__ x,
                                                  const float* __restrict__ W1,
                                                  int n) {
    __shared__ float Xs[128 * 36];   // [row][k_local] stride 36 (pad 4)
    __shared__ float Wsc[32 * 16];   // [k_local][col]

    int t    = threadIdx.x;
    int c    = t & 3;
    int rg   = t >> 2;
    int row0 = blockIdx.x * 128;

    float acc[4][4];
    #pragma unroll
    for (int i = 0; i < 4; i++)
        #pragma unroll
        for (int j = 0; j < 4; j++) acc[i][j] = 0.f;

    int sq  = t & 7;
    int sr  = t >> 3;
    int wkl = t >> 2;
    int wjj = (t & 3) * 4;

    #pragma unroll 1
    for (int ch = 0; ch < 16; ch++) {
        int k0 = ch * 32;
        __syncthreads();
        *(float4*)(Wsc + wkl * 16 + wjj) =
            *(const float4*)(W1 + (size_t)(k0 + wkl) * 16 + wjj);
        #pragma unroll
        for (int p = 0; p < 8; p++) {
            int rl = p * 16 + sr;
            int gr = row0 + rl; if (gr > n - 1) gr = n - 1;
            float4 v = __ldg((const float4*)(x + (size_t)gr * 512 + k0) + sq);
            *(float4*)(Xs + rl * 36 + sq * 4) = v;
        }
        __syncthreads();

        #pragma unroll
        for (int k4 = 0; k4 < 8; k4++) {
            float4 w0 = *(float4*)(Wsc + (k4 * 4 + 0) * 16 + c * 4);
            float4 w1 = *(float4*)(Wsc + (k4 * 4 + 1) * 16 + c * 4);
            float4 w2 = *(float4*)(Wsc + (k4 * 4 + 2) * 16 + c * 4);
            float4 w3 = *(float4*)(Wsc + (k4 * 4 + 3) * 16 + c * 4);
            #pragma unroll
            for (int i = 0; i < 4; i++) {
                float4 xv = *(float4*)(Xs + (rg + 32 * i) * 36 + k4 * 4);
                acc[i][0] += xv.x * w0.x + xv.y * w1.x + xv.z * w2.x + xv.w * w3.x;
                acc[i][1] += xv.x * w0.y + xv.y * w1.y + xv.z * w2.y + xv.w * w3.y;
                acc[i][2] += xv.x * w0.z + xv.y * w1.z + xv.z * w2.z + xv.w * w3.z;
                acc[i][3] += xv.x * w0.w + xv.y * w1.w + xv.z * w2.w + xv.w * w3.w;
            }
        }
    }

    #pragma unroll
    for (int i = 0; i < 4; i++) {
        int row = row0 + rg + 32 * i;
        if (row >= n) continue;
        float dv = rsqrtf((float)g_cnt[row] + 1.f);
        float4 o = make_float4(acc[i][0] * dv, acc[i][1] * dv,
                               acc[i][2] * dv, acc[i][3] * dv);
        *(float4*)(g_hs + (size_t)row * 16 + c * 4) = o;
    }
}

// ---- fused gather1 + layer-1 epilogue + layer-2 GEMM ---------------------------------
__global__ void __launch_bounds__(256) k_gl1(const float* __restrict__ b1,
                                             const float* __restrict__ W2,
                                             int n) {
    __shared__ float W2s[112];
    __shared__ float b1s[16];
    int t = threadIdx.x;
    if (t < 112) W2s[t] = W2[t];
    if (t < 16)  b1s[t] = b1[t];
    __syncthreads();

    int gi = blockIdx.x * 256 + t;
    int v  = gi >> 2;
    if (v >= n) return;
    int q   = gi & 3;
    int off = g_off[v];
    int cnt = g_cnt[v];

    float4 acc = make_float4(0.f, 0.f, 0.f, 0.f);
    int i = 0;
    for (; i + 2 <= cnt; i += 2) {
        int s0 = g_eadj[off + i];
        int s1 = g_eadj[off + i + 1];
        float4 a = __ldg((const float4*)(g_hs + (size_t)s0 * 16) + q);
        float4 b = __ldg((const float4*)(g_hs + (size_t)s1 * 16) + q);
        acc.x += a.x + b.x; acc.y += a.y + b.y;
        acc.z += a.z + b.z; acc.w += a.w + b.w;
    }
    if (i < cnt) {
        int s0 = g_eadj[off + i];
        float4 a = __ldg((const float4*)(g_hs + (size_t)s0 * 16) + q);
        acc.x += a.x; acc.y += a.y; acc.z += a.z; acc.w += a.w;
    }

    float dv = rsqrtf((float)cnt + 1.f);
    float4 self = *(const float4*)(g_hs + (size_t)v * 16 + q * 4);
    float h0 = fmaxf(fmaf(dv, acc.x + self.x, b1s[q * 4 + 0]), 0.f);
    float h1 = fmaxf(fmaf(dv, acc.y + self.y, b1s[q * 4 + 1]), 0.f);
    float h2 = fmaxf(fmaf(dv, acc.z + self.z, b1s[q * 4 + 2]), 0.f);
    float h3 = fmaxf(fmaf(dv, acc.w + self.w, b1s[q * 4 + 3]), 0.f);

    float o[7];
    #pragma unroll
    for (int j = 0; j < 7; j++) {
        const float* wq = W2s + (q * 4) * 7 + j;
        o[j] = h0 * wq[0] + h1 * wq[7] + h2 * wq[14] + h3 * wq[21];
    }
    #pragma unroll
    for (int j = 0; j < 7; j++) {
        o[j] += __shfl_xor_sync(0xffffffffu, o[j], 1);
        o[j] += __shfl_xor_sync(0xffffffffu, o[j], 2);
    }

    if (q == 0)
        *(float4*)(g_hs2 + (size_t)v * 8) =
            make_float4(o[0] * dv, o[1] * dv, o[2] * dv, o[3] * dv);
    else if (q == 1)
        *(float4*)(g_hs2 + (size_t)v * 8 + 4) =
            make_float4(o[4] * dv, o[5] * dv, o[6] * dv, 0.f);
}

// ---- fused gather2 + final (bias + log_softmax) ---------------------------------------
__global__ void __launch_bounds__(256) k_gl2(const float* __restrict__ b2,
                                             float* __restrict__ out, int n) {
    int gi = blockIdx.x * 256 + threadIdx.x;
    int v  = gi >> 1;
    if (v >= n) return;
    int q   = gi & 1;
    int off = g_off[v];
    int cnt = g_cnt[v];

    float4 acc = make_float4(0.f, 0.f, 0.f, 0.f);
    int i = 0;
    for (; i + 2 <= cnt; i += 2) {
        int s0 = g_eadj[off + i];
        int s1 = g_eadj[off + i + 1];
        float4 a = __ldg((const float4*)(g_hs2 + (size_t)s0 * 8) + q);
        float4 b = __ldg((const float4*)(g_hs2 + (size_t)s1 * 8) + q);
        acc.x += a.x + b.x; acc.y += a.y + b.y;
        acc.z += a.z + b.z; acc.w += a.w + b.w;
    }
    if (i < cnt) {
        int s0 = g_eadj[off + i];
        float4 a = __ldg((const float4*)(g_hs2 + (size_t)s0 * 8) + q);
        acc.x += a.x; acc.y += a.y; acc.z += a.z; acc.w += a.w;
    }

    float dv = rsqrtf((float)cnt + 1.f);
    float4 self = *(const float4*)(g_hs2 + (size_t)v * 8 + q * 4);
    float m0 = fmaf(dv, acc.x + self.x, __ldg(b2 + q * 4 + 0));
    float m1 = fmaf(dv, acc.y + self.y, __ldg(b2 + q * 4 + 1));
    float m2 = fmaf(dv, acc.z + self.z, __ldg(b2 + q * 4 + 2));
    float m3 = (q == 0) ? fmaf(dv, acc.w + self.w, __ldg(b2 + 3)) : -1e30f;

    float p0 = __shfl_xor_sync(0xffffffffu, m0, 1);
    float p1 = __shfl_xor_sync(0xffffffffu, m1, 1);
    float p2 = __shfl_xor_sync(0xffffffffu, m2, 1);
    float p3 = __shfl_xor_sync(0xffffffffu, m3, 1);

    float mx = fmaxf(fmaxf(fmaxf(m0, m1), fmaxf(m2, m3)),
                     fmaxf(fmaxf(p0, p1), fmaxf(p2, p3)));
    float s = expf(m0 - mx) + expf(m1 - mx) + expf(m2 - mx) +
              expf(p0 - mx) + expf(p1 - mx) + expf(p2 - mx);
    s += (q == 0) ? expf(m3 - mx) : expf(p3 - mx);
    float l = logf(s) + mx;

    float* ov = out + (size_t)v * 7 + q * 4;
    ov[0] = m0 - l;
    ov[1] = m1 - l;
    ov[2] = m2 - l;
    if (q == 0) ov[3] = m3 - l;
}

// ---------------------------------------------------------------------------
extern "C" void kernel_launch(void* const* d_in, const int* in_sizes, int n_in,
                              void* d_out, int out_size) {
    const float* x  = (const float*)d_in[0];
    const int*   ei = (const int*)d_in[1];      // int32 (JAX x64 disabled)
    const float* W1 = (const float*)d_in[2];
    const float* b1 = (const float*)d_in[3];
    const float* W2 = (const float*)d_in[4];
    const float* b2 = (const float*)d_in[5];

    int n = in_sizes[0] / 512;     // 100000
    int E = in_sizes[1] / 2;       // 3200000
    const int* src = ei;
    const int* dst = ei + E;

    // one-time host resources (no device memory); work is identical every call
    static cudaStream_t s2 = 0;
    static cudaEvent_t evFork = 0, evJoin = 0;
    if (!s2) {
        cudaStreamCreateWithFlags(&s2, cudaStreamNonBlocking);
        cudaEventCreateWithFlags(&evFork, cudaEventDisableTiming);
        cudaEventCreateWithFlags(&evJoin, cudaEventDisableTiming);
    }

    int nb = (n + 255) / 256;
    int e4 = (E + 3) / 4;
    int eb4 = (e4 + 255) / 256;

    k_zero <<<nb, 256>>>(n);
    k_count<<<eb4, 256>>>(dst, E);
    cudaEventRecord(evFork, 0);

    // side stream: CSR build (scan + place) — latency-bound, overlaps with GEMM1
    cudaStreamWaitEvent(s2, evFork, 0);
    k_scan <<<nb, 256, 0, s2>>>(n);
    k_place<<<eb4, 256, 0, s2>>>(src, dst, E);
    cudaEventRecord(evJoin, s2);

    // main stream: GEMM1 (fma-bound), independent of CSR adjacency
    k_gemm1<<<(n + 127) / 128, 128>>>(x, W1, n);
    cudaStreamWaitEvent(0, evJoin, 0);

    k_gl1  <<<(4 * n + 255) / 256, 256>>>(b1, W2, n);
    k_gl2  <<<(2 * n + 255) / 256, 256>>>(b2, (float*)d_out, n);
}